// round 2
// baseline (speedup 1.0000x reference)
#include <cuda_runtime.h>
#include <cuda_fp16.h>
#include <cstdint>

#define NFEAT   49152
#define NVFEAT  768
#define FTOUT   1024
#define FPP     32

// 96 MB fused table: fused[f][c] = fp16(W_ft[f][c] + W_fft[f % 768][c])
// Static __device__ scratch (allowed; no runtime allocation).
__device__ __half g_fused[(size_t)NFEAT * FTOUT];

// ---------------------------------------------------------------------------
// Kernel 1: build fused fp16 table. Grid = NFEAT blocks x 256 threads.
// Each thread handles 4 consecutive columns (one float4 per table).
// Traffic: read 192MB + 3MB (L2-cached), write 96MB  ->  DRAM-bound, ~36us.
// ---------------------------------------------------------------------------
__global__ __launch_bounds__(256) void fuse_kernel(const float* __restrict__ W_ft,
                                                   const float* __restrict__ W_fft) {
    const int f = blockIdx.x;
    const int c = threadIdx.x * 4;
    const float4 a = *(const float4*)(W_ft  + (size_t)f * FTOUT + c);
    const float4 b = *(const float4*)(W_fft + (size_t)(f % NVFEAT) * FTOUT + c);
    __half2 h0 = __floats2half2_rn(a.x + b.x, a.y + b.y);
    __half2 h1 = __floats2half2_rn(a.z + b.z, a.w + b.w);
    uint2 pack;
    pack.x = *reinterpret_cast<const unsigned int*>(&h0);
    pack.y = *reinterpret_cast<const unsigned int*>(&h1);
    *reinterpret_cast<uint2*>(g_fused + (size_t)f * FTOUT + c) = pack;
}

// ---------------------------------------------------------------------------
// Kernel 2: per-batch gather + accumulate + clip + output layer + sigmoid.
// One CTA per batch element, 128 threads, each thread owns 8 columns.
// Per feature per side: one LDG.128 (8 halfs) from the fused table.
// Gather traffic: 8192 * 64 rows * 2KB = 1.07 GB, mostly L2 hits.
// ---------------------------------------------------------------------------
__global__ __launch_bounds__(128) void nnue_kernel(
    const float* __restrict__ values,
    const int*   __restrict__ stm_feat,
    const int*   __restrict__ nstm_feat,
    const float* __restrict__ b_ft,
    const float* __restrict__ b_fft,
    const float* __restrict__ W_out,
    const float* __restrict__ b_out,
    float*       __restrict__ out)
{
    __shared__ int   s_stm[FPP];
    __shared__ int   s_nstm[FPP];
    __shared__ float s_val[FPP];
    __shared__ float s_red[4];

    const int b   = blockIdx.x;
    const int tid = threadIdx.x;

    // Coalesced staging: threads 0..31 -> stm, 32..63 -> nstm, 64..95 -> values.
    if (tid < FPP) {
        s_stm[tid] = stm_feat[b * FPP + tid];
    } else if (tid < 2 * FPP) {
        s_nstm[tid - FPP] = nstm_feat[b * FPP + (tid - FPP)];
    } else if (tid < 3 * FPP) {
        s_val[tid - 2 * FPP] = values[b * FPP + (tid - 2 * FPP)];
    }
    __syncthreads();

    const int c = tid * 8;  // this thread's column base (0..1016)

    float acc_s[8];
    float acc_n[8];
#pragma unroll
    for (int j = 0; j < 8; ++j) { acc_s[j] = 0.f; acc_n[j] = 0.f; }

#pragma unroll 4
    for (int f = 0; f < FPP; ++f) {
        const float v  = s_val[f];
        const uint4 ws = *(const uint4*)(g_fused + (size_t)s_stm[f]  * FTOUT + c);
        const uint4 wn = *(const uint4*)(g_fused + (size_t)s_nstm[f] * FTOUT + c);
        const __half2* hs = reinterpret_cast<const __half2*>(&ws);
        const __half2* hn = reinterpret_cast<const __half2*>(&wn);
#pragma unroll
        for (int j = 0; j < 4; ++j) {
            float2 fs = __half22float2(hs[j]);
            float2 fn = __half22float2(hn[j]);
            acc_s[2 * j]     = fmaf(fs.x, v, acc_s[2 * j]);
            acc_s[2 * j + 1] = fmaf(fs.y, v, acc_s[2 * j + 1]);
            acc_n[2 * j]     = fmaf(fn.x, v, acc_n[2 * j]);
            acc_n[2 * j + 1] = fmaf(fn.y, v, acc_n[2 * j + 1]);
        }
    }

    // Epilogue: bias + clip(0,1) + dot with W_out (concat order: [stm | nstm])
    float partial = 0.f;
#pragma unroll
    for (int j = 0; j < 8; ++j) {
        const float bias = b_ft[c + j] + b_fft[c + j];
        const float hs = fminf(fmaxf(acc_s[j] + bias, 0.f), 1.f);
        const float hn = fminf(fmaxf(acc_n[j] + bias, 0.f), 1.f);
        partial = fmaf(hs, W_out[c + j], partial);
        partial = fmaf(hn, W_out[FTOUT + c + j], partial);
    }

    // Block reduction: warp shuffle then cross-warp via shared.
#pragma unroll
    for (int o = 16; o > 0; o >>= 1)
        partial += __shfl_down_sync(0xFFFFFFFFu, partial, o);
    if ((tid & 31) == 0) s_red[tid >> 5] = partial;
    __syncthreads();
    if (tid == 0) {
        const float x = s_red[0] + s_red[1] + s_red[2] + s_red[3] + b_out[0];
        out[b] = 1.f / (1.f + expf(-x));
    }
}

// ---------------------------------------------------------------------------
// Launch wrapper. Input order (metadata): values, stm_feat, nstm_feat,
// batch_idx, W_ft, b_ft, W_fft, b_fft, W_out, b_out, size.
// batch_idx is repeat(arange(B), FPP) by construction -> implicit in layout.
// ---------------------------------------------------------------------------
extern "C" void kernel_launch(void* const* d_in, const int* in_sizes, int n_in,
                              void* d_out, int out_size) {
    const float* values    = (const float*)d_in[0];
    const int*   stm_feat  = (const int*)  d_in[1];
    const int*   nstm_feat = (const int*)  d_in[2];
    // d_in[3] = batch_idx (unused: contiguous groups of FPP per batch element)
    const float* W_ft      = (const float*)d_in[4];
    const float* b_ft      = (const float*)d_in[5];
    const float* W_fft     = (const float*)d_in[6];
    const float* b_fft     = (const float*)d_in[7];
    const float* W_out     = (const float*)d_in[8];
    const float* b_out     = (const float*)d_in[9];
    float*       out       = (float*)d_out;

    const int B = out_size;  // 8192

    fuse_kernel<<<NFEAT, 256>>>(W_ft, W_fft);
    nnue_kernel<<<B, 128>>>(values, stm_feat, nstm_feat,
                            b_ft, b_fft, W_out, b_out, out);
}

// round 8
// speedup vs baseline: 1.0248x; 1.0248x over previous
#include <cuda_runtime.h>
#include <cstdint>

#define NFEAT   49152
#define NVFEAT  768
#define FTOUT   1024
#define FPP     32

// 48 MB int8 fused table (stored as packed uint32, 4 cols/word) + per-row scale.
// fused[f][c] = round((W_ft[f][c] + W_fft[f%768][c]) / s_f) + 128, s_f = rowmax/127.
__device__ unsigned int g_q[(size_t)NFEAT * (FTOUT / 4)];
__device__ float        g_scale[NFEAT];

// ---------------------------------------------------------------------------
// Kernel 1: fuse + per-row int8 quantize. One CTA (256 thr) per feature row.
// Each thread: 4 columns. Block max-reduce -> scale -> quantize -> pack.
// DRAM: read 192+3 MB, write 48 MB  -> ~35-40us.
// ---------------------------------------------------------------------------
__global__ __launch_bounds__(256) void fuse_q8_kernel(const float* __restrict__ W_ft,
                                                      const float* __restrict__ W_fft) {
    const int f   = blockIdx.x;
    const int tid = threadIdx.x;
    const int c   = tid * 4;

    const float4 a = *(const float4*)(W_ft  + (size_t)f * FTOUT + c);
    const float4 b = *(const float4*)(W_fft + (size_t)(f % NVFEAT) * FTOUT + c);
    const float w0 = a.x + b.x, w1 = a.y + b.y, w2 = a.z + b.z, w3 = a.w + b.w;

    // Row max(|w|) reduction: warp shuffle, then cross-warp via shared.
    float m = fmaxf(fmaxf(fabsf(w0), fabsf(w1)), fmaxf(fabsf(w2), fabsf(w3)));
    __shared__ float s_m[8];
#pragma unroll
    for (int o = 16; o > 0; o >>= 1)
        m = fmaxf(m, __shfl_xor_sync(0xFFFFFFFFu, m, o));
    if ((tid & 31) == 0) s_m[tid >> 5] = m;
    __syncthreads();
    const float rm = fmaxf(fmaxf(fmaxf(s_m[0], s_m[1]), fmaxf(s_m[2], s_m[3])),
                           fmaxf(fmaxf(s_m[4], s_m[5]), fmaxf(s_m[6], s_m[7])));

    const float s   = fmaxf(rm, 1e-20f) * (1.0f / 127.0f);
    const float inv = 1.0f / s;

    int u0 = __float2int_rn(w0 * inv) + 128;
    int u1 = __float2int_rn(w1 * inv) + 128;
    int u2 = __float2int_rn(w2 * inv) + 128;
    int u3 = __float2int_rn(w3 * inv) + 128;
    u0 = min(255, max(0, u0)); u1 = min(255, max(0, u1));
    u2 = min(255, max(0, u2)); u3 = min(255, max(0, u3));

    g_q[(size_t)f * (FTOUT / 4) + tid] =
        (unsigned)u0 | ((unsigned)u1 << 8) | ((unsigned)u2 << 16) | ((unsigned)u3 << 24);
    if (tid == 0) g_scale[f] = s;
}

// ---------------------------------------------------------------------------
// Kernel 2: per-batch gather (int8 rows, 1KB each) + decode + accumulate +
// clip + output layer + sigmoid. One CTA per batch element, 128 threads,
// 8 columns/thread -> one LDG.64 per side per feature.
// Decode: PRMT byte -> 0x4B0000uu float (8388608+u, exact), FADD -C,
// FFMA x (scale*value). No I2F anywhere.
// Gather L2 traffic: 8192 * 64KB = 537 MB; 48MB table is L2-resident.
// ---------------------------------------------------------------------------
__global__ __launch_bounds__(128) void nnue_q8_kernel(
    const float* __restrict__ values,
    const int*   __restrict__ stm_feat,
    const int*   __restrict__ nstm_feat,
    const float* __restrict__ b_ft,
    const float* __restrict__ b_fft,
    const float* __restrict__ W_out,
    const float* __restrict__ b_out,
    float*       __restrict__ out)
{
    __shared__ int   s_if[2 * FPP];   // [0..31] stm idx, [32..63] nstm idx
    __shared__ float s_mf[2 * FPP];   // per-slot scale * value
    __shared__ float s_red[4];

    const int b   = blockIdx.x;
    const int tid = threadIdx.x;

    if (tid < 2 * FPP) {
        const int j   = tid & 31;
        const int idx = (tid < FPP) ? stm_feat[b * FPP + j] : nstm_feat[b * FPP + j];
        s_if[tid] = idx;
        s_mf[tid] = g_scale[idx] * values[b * FPP + j];
    }
    __syncthreads();

    const int wbase = tid * 2;        // word offset within a 256-word row
    const int c     = tid * 8;        // column base

    float acc[16];                    // [0..7] stm, [8..15] nstm
#pragma unroll
    for (int j = 0; j < 16; ++j) acc[j] = 0.f;

    const float C = 8388736.0f;       // 2^23 + 128

#pragma unroll 8
    for (int f = 0; f < FPP; ++f) {
        const int   is = s_if[f];
        const float ms = s_mf[f];
        const int   in = s_if[FPP + f];
        const float mn = s_mf[FPP + f];

        const uint2 ws = *(const uint2*)(g_q + (size_t)is * (FTOUT / 4) + wbase);
        const uint2 wn = *(const uint2*)(g_q + (size_t)in * (FTOUT / 4) + wbase);

#pragma unroll
        for (int i = 0; i < 4; ++i) {
            const unsigned sel = 0x7540u + (unsigned)i;  // [b_i, 0x00, 0x00, 0x4B]
            float fs0 = __int_as_float(__byte_perm(ws.x, 0x4B000000u, sel)) - C;
            float fs1 = __int_as_float(__byte_perm(ws.y, 0x4B000000u, sel)) - C;
            float fn0 = __int_as_float(__byte_perm(wn.x, 0x4B000000u, sel)) - C;
            float fn1 = __int_as_float(__byte_perm(wn.y, 0x4B000000u, sel)) - C;
            acc[i]      = fmaf(fs0, ms, acc[i]);
            acc[4 + i]  = fmaf(fs1, ms, acc[4 + i]);
            acc[8 + i]  = fmaf(fn0, mn, acc[8 + i]);
            acc[12 + i] = fmaf(fn1, mn, acc[12 + i]);
        }
    }

    // Epilogue: bias + clip(0,1) + dot with W_out (concat order: [stm | nstm])
    float partial = 0.f;
#pragma unroll
    for (int j = 0; j < 8; ++j) {
        const float bias = b_ft[c + j] + b_fft[c + j];
        const float hs = fminf(fmaxf(acc[j]     + bias, 0.f), 1.f);
        const float hn = fminf(fmaxf(acc[8 + j] + bias, 0.f), 1.f);
        partial = fmaf(hs, W_out[c + j], partial);
        partial = fmaf(hn, W_out[FTOUT + c + j], partial);
    }

#pragma unroll
    for (int o = 16; o > 0; o >>= 1)
        partial += __shfl_down_sync(0xFFFFFFFFu, partial, o);
    if ((tid & 31) == 0) s_red[tid >> 5] = partial;
    __syncthreads();
    if (tid == 0) {
        const float x = s_red[0] + s_red[1] + s_red[2] + s_red[3] + b_out[0];
        out[b] = 1.f / (1.f + expf(-x));
    }
}

// ---------------------------------------------------------------------------
// Launch wrapper. Input order: values, stm_feat, nstm_feat, batch_idx,
// W_ft, b_ft, W_fft, b_fft, W_out, b_out, size.
// batch_idx = repeat(arange(B), FPP) -> implicit in layout.
// ---------------------------------------------------------------------------
extern "C" void kernel_launch(void* const* d_in, const int* in_sizes, int n_in,
                              void* d_out, int out_size) {
    const float* values    = (const float*)d_in[0];
    const int*   stm_feat  = (const int*)  d_in[1];
    const int*   nstm_feat = (const int*)  d_in[2];
    // d_in[3] = batch_idx (unused)
    const float* W_ft      = (const float*)d_in[4];
    const float* b_ft      = (const float*)d_in[5];
    const float* W_fft     = (const float*)d_in[6];
    const float* b_fft     = (const float*)d_in[7];
    const float* W_out     = (const float*)d_in[8];
    const float* b_out     = (const float*)d_in[9];
    float*       out       = (float*)d_out;

    const int B = out_size;  // 8192

    fuse_q8_kernel<<<NFEAT, 256>>>(W_ft, W_fft);
    nnue_q8_kernel<<<B, 128>>>(values, stm_feat, nstm_feat,
                               b_ft, b_fft, W_out, b_out, out);
}

// round 9
// speedup vs baseline: 1.1968x; 1.1679x over previous
#include <cuda_runtime.h>
#include <cstdint>

#define NFEAT   49152
#define NVFEAT  768
#define FTOUT   1024
#define FPP     32

// 48 MB int8 fused table (packed uint32, 4 cols/word, bias +128) + per-row scale.
// fused[f][c] = round((W_ft[f][c] + W_fft[f%768][c]) / s_f) + 128, s_f = rowmax/127.
__device__ unsigned int g_q[(size_t)NFEAT * (FTOUT / 4)];
__device__ float        g_scale[NFEAT];

// ---------------------------------------------------------------------------
// Kernel 1: fuse + per-row int8 quantize. Warp-per-row, 8 rows per 256-thr
// CTA, grid = 6144. No __syncthreads: warp-shuffle max reduction only.
// Each lane: 8 float4 (32 cols), coalesced 128B per step. DRAM ~240MB.
// ---------------------------------------------------------------------------
__global__ __launch_bounds__(256) void fuse_q8_kernel(const float* __restrict__ W_ft,
                                                      const float* __restrict__ W_fft) {
    const int f    = blockIdx.x * 8 + (threadIdx.x >> 5);
    const int lane = threadIdx.x & 31;
    const float* __restrict__ pa = W_ft  + (size_t)f * FTOUT;
    const float* __restrict__ pb = W_fft + (size_t)(f % NVFEAT) * FTOUT;

    float w[32];
    float m = 0.f;
#pragma unroll
    for (int j = 0; j < 8; ++j) {
        const float4 a = *(const float4*)(pa + (j * 32 + lane) * 4);
        const float4 b = *(const float4*)(pb + (j * 32 + lane) * 4);
        w[4 * j + 0] = a.x + b.x;
        w[4 * j + 1] = a.y + b.y;
        w[4 * j + 2] = a.z + b.z;
        w[4 * j + 3] = a.w + b.w;
        m = fmaxf(m, fmaxf(fmaxf(fabsf(w[4 * j]), fabsf(w[4 * j + 1])),
                           fmaxf(fabsf(w[4 * j + 2]), fabsf(w[4 * j + 3]))));
    }

#pragma unroll
    for (int o = 16; o > 0; o >>= 1)
        m = fmaxf(m, __shfl_xor_sync(0xFFFFFFFFu, m, o));

    const float s   = fmaxf(m, 1e-20f) * (1.0f / 127.0f);
    const float inv = 1.0f / s;

#pragma unroll
    for (int j = 0; j < 8; ++j) {
        int u0 = __float2int_rn(w[4 * j + 0] * inv) + 128;
        int u1 = __float2int_rn(w[4 * j + 1] * inv) + 128;
        int u2 = __float2int_rn(w[4 * j + 2] * inv) + 128;
        int u3 = __float2int_rn(w[4 * j + 3] * inv) + 128;
        u0 = min(255, max(0, u0)); u1 = min(255, max(0, u1));
        u2 = min(255, max(0, u2)); u3 = min(255, max(0, u3));
        g_q[(size_t)f * (FTOUT / 4) + j * 32 + lane] =
            (unsigned)u0 | ((unsigned)u1 << 8) | ((unsigned)u2 << 16) | ((unsigned)u3 << 24);
    }
    if (lane == 0) g_scale[f] = s;
}

// ---------------------------------------------------------------------------
// Kernel 2: per-batch gather + decode + accumulate + clip + output + sigmoid.
// One CTA per batch element, 128 threads, 8 cols/thread, LDG.64/side/feature.
// Decode (1 PRMT + 1 FMA per element, no FADD): PRMT builds float(32768+u)
// exactly (magic 0x47000000, u at mantissa byte 1); accumulate raw with FMA;
// subtract C*S once per column at the end (S = sum of scale*value per side).
// alu pipe: ~1 op/elt (was 2) -> issue-bound pressure removed.
// ---------------------------------------------------------------------------
__global__ __launch_bounds__(128) void nnue_q8_kernel(
    const float* __restrict__ values,
    const int*   __restrict__ stm_feat,
    const int*   __restrict__ nstm_feat,
    const float* __restrict__ b_ft,
    const float* __restrict__ b_fft,
    const float* __restrict__ W_out,
    const float* __restrict__ b_out,
    float*       __restrict__ out)
{
    __shared__ int   s_if[2 * FPP];   // [0..31] stm idx, [32..63] nstm idx
    __shared__ float s_mf[2 * FPP];   // per-slot scale * value
    __shared__ float s_red[4];

    const int b   = blockIdx.x;
    const int tid = threadIdx.x;

    if (tid < 2 * FPP) {
        const int j   = tid & 31;
        const int idx = (tid < FPP) ? stm_feat[b * FPP + j] : nstm_feat[b * FPP + j];
        s_if[tid] = idx;
        s_mf[tid] = g_scale[idx] * values[b * FPP + j];
    }
    __syncthreads();

    const int wbase = tid * 2;        // word offset within a 256-word row
    const int c     = tid * 8;        // column base

    float acc[16];                    // [0..7] stm, [8..15] nstm (raw, biased)
#pragma unroll
    for (int j = 0; j < 16; ++j) acc[j] = 0.f;

#pragma unroll 8
    for (int f = 0; f < FPP; ++f) {
        const int   is = s_if[f];
        const float ms = s_mf[f];
        const int   in = s_if[FPP + f];
        const float mn = s_mf[FPP + f];

        const uint2 ws = *(const uint2*)(g_q + (size_t)is * (FTOUT / 4) + wbase);
        const uint2 wn = *(const uint2*)(g_q + (size_t)in * (FTOUT / 4) + wbase);

#pragma unroll
        for (int i = 0; i < 4; ++i) {
            const unsigned sel = 0x7404u | ((unsigned)i << 4);  // [0, b_i, 0, 0x47]
            float fs0 = __int_as_float(__byte_perm(ws.x, 0x47000000u, sel));
            float fs1 = __int_as_float(__byte_perm(ws.y, 0x47000000u, sel));
            float fn0 = __int_as_float(__byte_perm(wn.x, 0x47000000u, sel));
            float fn1 = __int_as_float(__byte_perm(wn.y, 0x47000000u, sel));
            acc[i]      = fmaf(fs0, ms, acc[i]);
            acc[4 + i]  = fmaf(fs1, ms, acc[4 + i]);
            acc[8 + i]  = fmaf(fn0, mn, acc[8 + i]);
            acc[12 + i] = fmaf(fn1, mn, acc[12 + i]);
        }
    }

    // Deferred magic-bias removal: acc_true = acc_raw - (32768+128) * sum(ms).
    float S_s = 0.f, S_n = 0.f;
#pragma unroll
    for (int f = 0; f < FPP; ++f) { S_s += s_mf[f]; S_n += s_mf[FPP + f]; }
    const float C = 32896.0f;          // 2^15 + 128
    const float corr_s = C * S_s;
    const float corr_n = C * S_n;

    // Epilogue: bias + clip(0,1) + dot with W_out (concat order: [stm | nstm])
    float partial = 0.f;
#pragma unroll
    for (int j = 0; j < 8; ++j) {
        const float bias = b_ft[c + j] + b_fft[c + j];
        const float hs = fminf(fmaxf(acc[j]     - corr_s + bias, 0.f), 1.f);
        const float hn = fminf(fmaxf(acc[8 + j] - corr_n + bias, 0.f), 1.f);
        partial = fmaf(hs, W_out[c + j], partial);
        partial = fmaf(hn, W_out[FTOUT + c + j], partial);
    }

#pragma unroll
    for (int o = 16; o > 0; o >>= 1)
        partial += __shfl_down_sync(0xFFFFFFFFu, partial, o);
    if ((tid & 31) == 0) s_red[tid >> 5] = partial;
    __syncthreads();
    if (tid == 0) {
        const float x = s_red[0] + s_red[1] + s_red[2] + s_red[3] + b_out[0];
        out[b] = 1.f / (1.f + expf(-x));
    }
}

// ---------------------------------------------------------------------------
// Launch wrapper. Input order: values, stm_feat, nstm_feat, batch_idx,
// W_ft, b_ft, W_fft, b_fft, W_out, b_out, size.
// batch_idx = repeat(arange(B), FPP) -> implicit in layout.
// ---------------------------------------------------------------------------
extern "C" void kernel_launch(void* const* d_in, const int* in_sizes, int n_in,
                              void* d_out, int out_size) {
    const float* values    = (const float*)d_in[0];
    const int*   stm_feat  = (const int*)  d_in[1];
    const int*   nstm_feat = (const int*)  d_in[2];
    // d_in[3] = batch_idx (unused)
    const float* W_ft      = (const float*)d_in[4];
    const float* b_ft      = (const float*)d_in[5];
    const float* W_fft     = (const float*)d_in[6];
    const float* b_fft     = (const float*)d_in[7];
    const float* W_out     = (const float*)d_in[8];
    const float* b_out     = (const float*)d_in[9];
    float*       out       = (float*)d_out;

    const int B = out_size;  // 8192

    fuse_q8_kernel<<<NFEAT / 8, 256>>>(W_ft, W_fft);
    nnue_q8_kernel<<<B, 128>>>(values, stm_feat, nstm_feat,
                               b_ft, b_fft, W_out, b_out, out);
}

// round 10
// speedup vs baseline: 1.3896x; 1.1610x over previous
#include <cuda_runtime.h>
#include <cstdint>

#define NFEAT   49152
#define NVFEAT  768
#define FTOUT   1024
#define FPP     32

// 48 MB int8 fused table (packed uint32, 4 cols/word, bias +128) + per-row scale.
__device__ unsigned int g_q[(size_t)NFEAT * (FTOUT / 4)];
__device__ float        g_scale[NFEAT];

// ---------------------------------------------------------------------------
// Kernel 1: fuse + per-row int8 quantize. Warp-per-row, 8 rows/CTA. ~39.5us
// measured, near DRAM bound (243 MB). Unchanged from R9.
// ---------------------------------------------------------------------------
__global__ __launch_bounds__(256) void fuse_q8_kernel(const float* __restrict__ W_ft,
                                                      const float* __restrict__ W_fft) {
    const int f    = blockIdx.x * 8 + (threadIdx.x >> 5);
    const int lane = threadIdx.x & 31;
    const float* __restrict__ pa = W_ft  + (size_t)f * FTOUT;
    const float* __restrict__ pb = W_fft + (size_t)(f % NVFEAT) * FTOUT;

    float w[32];
    float m = 0.f;
#pragma unroll
    for (int j = 0; j < 8; ++j) {
        const float4 a = *(const float4*)(pa + (j * 32 + lane) * 4);
        const float4 b = *(const float4*)(pb + (j * 32 + lane) * 4);
        w[4 * j + 0] = a.x + b.x;
        w[4 * j + 1] = a.y + b.y;
        w[4 * j + 2] = a.z + b.z;
        w[4 * j + 3] = a.w + b.w;
        m = fmaxf(m, fmaxf(fmaxf(fabsf(w[4 * j]), fabsf(w[4 * j + 1])),
                           fmaxf(fabsf(w[4 * j + 2]), fabsf(w[4 * j + 3]))));
    }
#pragma unroll
    for (int o = 16; o > 0; o >>= 1)
        m = fmaxf(m, __shfl_xor_sync(0xFFFFFFFFu, m, o));

    const float s   = fmaxf(m, 1e-20f) * (1.0f / 127.0f);
    const float inv = 1.0f / s;

#pragma unroll
    for (int j = 0; j < 8; ++j) {
        int u0 = __float2int_rn(w[4 * j + 0] * inv) + 128;
        int u1 = __float2int_rn(w[4 * j + 1] * inv) + 128;
        int u2 = __float2int_rn(w[4 * j + 2] * inv) + 128;
        int u3 = __float2int_rn(w[4 * j + 3] * inv) + 128;
        u0 = min(255, max(0, u0)); u1 = min(255, max(0, u1));
        u2 = min(255, max(0, u2)); u3 = min(255, max(0, u3));
        g_q[(size_t)f * (FTOUT / 4) + j * 32 + lane] =
            (unsigned)u0 | ((unsigned)u1 << 8) | ((unsigned)u2 << 16) | ((unsigned)u3 << 24);
    }
    if (lane == 0) g_scale[f] = s;
}

// ---------------------------------------------------------------------------
// Kernel 2: 2 batches per 128-thr CTA; 64 threads per batch, 16 cols/thread.
// Per feature-side: one LDS.64 (meta: word-offset + ms) and one LDG.128.
// Decode: 1 PRMT (magic 0x47000000 -> float(32768+u)) + 1 FFMA per element;
// bias removed once per column via corr = 32896 * sum(ms) (shuffle-reduced
// at staging). Numerics identical to R9.
// ---------------------------------------------------------------------------
__global__ __launch_bounds__(128) void nnue_q8_kernel(
    const float* __restrict__ values,
    const int*   __restrict__ stm_feat,
    const int*   __restrict__ nstm_feat,
    const float* __restrict__ b_ft,
    const float* __restrict__ b_fft,
    const float* __restrict__ W_out,
    const float* __restrict__ b_out,
    float*       __restrict__ out)
{
    __shared__ int2  s_meta[128];  // [bsel*64 + slot]: slot 0..31 stm, 32..63 nstm
    __shared__ float s_S[4];       // warp w reduced sum(ms): w0=b0stm w1=b0nstm w2=b1stm w3=b1nstm
    __shared__ float s_red[4];     // epilogue partials per warp

    const int tid  = threadIdx.x;
    const int bsel = tid >> 6;                 // which of the 2 batches
    const int t    = tid & 63;                 // thread-in-batch

    // ---- staging: one (offset, ms) entry per thread; warp-reduce sum(ms) ----
    {
        const int bb   = blockIdx.x * 2 + bsel;
        const int slot = t;                    // 0..31 stm, 32..63 nstm
        const int j    = slot & 31;
        const int idx  = (slot < 32) ? stm_feat[bb * FPP + j] : nstm_feat[bb * FPP + j];
        const float ms = g_scale[idx] * values[bb * FPP + j];
        s_meta[tid] = make_int2(idx * (FTOUT / 4), __float_as_int(ms));
        float S = ms;
#pragma unroll
        for (int o = 16; o > 0; o >>= 1)
            S += __shfl_xor_sync(0xFFFFFFFFu, S, o);
        if ((tid & 31) == 0) s_S[tid >> 5] = S;
    }
    __syncthreads();

    const int wbase = t * 4;                   // this thread's first word (16 cols)
    const int c     = t * 16;                  // column base

    float acc_s[16], acc_n[16];
#pragma unroll
    for (int j = 0; j < 16; ++j) { acc_s[j] = 0.f; acc_n[j] = 0.f; }

#pragma unroll 4
    for (int f = 0; f < FPP; ++f) {
        const int2 m_s = s_meta[bsel * 64 + f];
        const int2 m_n = s_meta[bsel * 64 + 32 + f];
        const float ms = __int_as_float(m_s.y);
        const float mn = __int_as_float(m_n.y);
        const uint4 ws = *(const uint4*)(g_q + m_s.x + wbase);
        const uint4 wn = *(const uint4*)(g_q + m_n.x + wbase);
        const unsigned wsa[4] = {ws.x, ws.y, ws.z, ws.w};
        const unsigned wna[4] = {wn.x, wn.y, wn.z, wn.w};
#pragma unroll
        for (int k = 0; k < 4; ++k) {
#pragma unroll
            for (int i = 0; i < 4; ++i) {
                const unsigned sel = 0x7404u | ((unsigned)i << 4);  // [0, b_i, 0, 0x47]
                const float fs = __int_as_float(__byte_perm(wsa[k], 0x47000000u, sel));
                const float fn = __int_as_float(__byte_perm(wna[k], 0x47000000u, sel));
                acc_s[4 * k + i] = fmaf(fs, ms, acc_s[4 * k + i]);
                acc_n[4 * k + i] = fmaf(fn, mn, acc_n[4 * k + i]);
            }
        }
    }

    // Deferred magic-bias removal: true = raw - (32768+128) * sum(ms).
    const float C      = 32896.0f;
    const float corr_s = C * s_S[bsel * 2 + 0];
    const float corr_n = C * s_S[bsel * 2 + 1];

    // Epilogue: bias + clip(0,1) + dot with W_out ([stm | nstm] concat).
    float partial = 0.f;
#pragma unroll
    for (int q = 0; q < 4; ++q) {
        const float4 bf = *(const float4*)(b_ft  + c + 4 * q);
        const float4 bg = *(const float4*)(b_fft + c + 4 * q);
        const float4 wo_s = *(const float4*)(W_out + c + 4 * q);
        const float4 wo_n = *(const float4*)(W_out + FTOUT + c + 4 * q);
        const float bias0 = bf.x + bg.x, bias1 = bf.y + bg.y;
        const float bias2 = bf.z + bg.z, bias3 = bf.w + bg.w;
        const int j = 4 * q;
        float hs, hn;
        hs = fminf(fmaxf(acc_s[j+0] - corr_s + bias0, 0.f), 1.f);
        hn = fminf(fmaxf(acc_n[j+0] - corr_n + bias0, 0.f), 1.f);
        partial = fmaf(hs, wo_s.x, fmaf(hn, wo_n.x, partial));
        hs = fminf(fmaxf(acc_s[j+1] - corr_s + bias1, 0.f), 1.f);
        hn = fminf(fmaxf(acc_n[j+1] - corr_n + bias1, 0.f), 1.f);
        partial = fmaf(hs, wo_s.y, fmaf(hn, wo_n.y, partial));
        hs = fminf(fmaxf(acc_s[j+2] - corr_s + bias2, 0.f), 1.f);
        hn = fminf(fmaxf(acc_n[j+2] - corr_n + bias2, 0.f), 1.f);
        partial = fmaf(hs, wo_s.z, fmaf(hn, wo_n.z, partial));
        hs = fminf(fmaxf(acc_s[j+3] - corr_s + bias3, 0.f), 1.f);
        hn = fminf(fmaxf(acc_n[j+3] - corr_n + bias3, 0.f), 1.f);
        partial = fmaf(hs, wo_s.w, fmaf(hn, wo_n.w, partial));
    }

    // Reduce: each warp covers 32 of its batch's 64 threads.
#pragma unroll
    for (int o = 16; o > 0; o >>= 1)
        partial += __shfl_down_sync(0xFFFFFFFFu, partial, o);
    if ((tid & 31) == 0) s_red[tid >> 5] = partial;
    __syncthreads();
    if (t == 0) {
        const float x = s_red[bsel * 2] + s_red[bsel * 2 + 1] + b_out[0];
        out[blockIdx.x * 2 + bsel] = 1.f / (1.f + expf(-x));
    }
}

// ---------------------------------------------------------------------------
// Launch wrapper. Input order: values, stm_feat, nstm_feat, batch_idx,
// W_ft, b_ft, W_fft, b_fft, W_out, b_out, size.
// batch_idx = repeat(arange(B), FPP) -> implicit in layout.
// ---------------------------------------------------------------------------
extern "C" void kernel_launch(void* const* d_in, const int* in_sizes, int n_in,
                              void* d_out, int out_size) {
    const float* values    = (const float*)d_in[0];
    const int*   stm_feat  = (const int*)  d_in[1];
    const int*   nstm_feat = (const int*)  d_in[2];
    // d_in[3] = batch_idx (unused)
    const float* W_ft      = (const float*)d_in[4];
    const float* b_ft      = (const float*)d_in[5];
    const float* W_fft     = (const float*)d_in[6];
    const float* b_fft     = (const float*)d_in[7];
    const float* W_out     = (const float*)d_in[8];
    const float* b_out     = (const float*)d_in[9];
    float*       out       = (float*)d_out;

    const int B = out_size;  // 8192

    fuse_q8_kernel<<<NFEAT / 8, 256>>>(W_ft, W_fft);
    nnue_q8_kernel<<<B / 2, 128>>>(values, stm_feat, nstm_feat,
                                   b_ft, b_fft, W_out, b_out, out);
}

// round 11
// speedup vs baseline: 1.5055x; 1.0834x over previous
#include <cuda_runtime.h>
#include <cstdint>

#define NFEAT   49152
#define NVFEAT  768
#define FTOUT   1024
#define FPP     32

// 48 MB int8 fused table (packed uint32, 4 cols/word, bias +128) + per-row scale.
__device__ unsigned int g_q[(size_t)NFEAT * (FTOUT / 4)];
__device__ float        g_scale[NFEAT];

__device__ __forceinline__ int dp4a_us(unsigned a, unsigned b, int c) {
    int d;
    asm("dp4a.u32.s32 %0, %1, %2, %3;" : "=r"(d) : "r"(a), "r"(b), "r"(c));
    return d;
}

// 4x4 byte transpose (8 PRMT) + 4 dp4a: accumulate 4 features x 4 columns.
#define TR_DP(a_, b_, c_, d_, mv_, A) { \
    const unsigned t0 = __byte_perm(a_, b_, 0x5140u); \
    const unsigned t1 = __byte_perm(a_, b_, 0x7362u); \
    const unsigned t2 = __byte_perm(c_, d_, 0x5140u); \
    const unsigned t3 = __byte_perm(c_, d_, 0x7362u); \
    (A)[0] = dp4a_us(__byte_perm(t0, t2, 0x5410u), mv_, (A)[0]); \
    (A)[1] = dp4a_us(__byte_perm(t0, t2, 0x7632u), mv_, (A)[1]); \
    (A)[2] = dp4a_us(__byte_perm(t1, t3, 0x5410u), mv_, (A)[2]); \
    (A)[3] = dp4a_us(__byte_perm(t1, t3, 0x7632u), mv_, (A)[3]); }

// ---------------------------------------------------------------------------
// Kernel 1: fuse + per-row int8 quantize. Warp-per-row, 8 rows/CTA.
// ~39.4us measured, ~6.1 TB/s DRAM -> near HBM-bound. Unchanged.
// ---------------------------------------------------------------------------
__global__ __launch_bounds__(256) void fuse_q8_kernel(const float* __restrict__ W_ft,
                                                      const float* __restrict__ W_fft) {
    const int f    = blockIdx.x * 8 + (threadIdx.x >> 5);
    const int lane = threadIdx.x & 31;
    const float* __restrict__ pa = W_ft  + (size_t)f * FTOUT;
    const float* __restrict__ pb = W_fft + (size_t)(f % NVFEAT) * FTOUT;

    float w[32];
    float m = 0.f;
#pragma unroll
    for (int j = 0; j < 8; ++j) {
        const float4 a = *(const float4*)(pa + (j * 32 + lane) * 4);
        const float4 b = *(const float4*)(pb + (j * 32 + lane) * 4);
        w[4 * j + 0] = a.x + b.x;
        w[4 * j + 1] = a.y + b.y;
        w[4 * j + 2] = a.z + b.z;
        w[4 * j + 3] = a.w + b.w;
        m = fmaxf(m, fmaxf(fmaxf(fabsf(w[4 * j]), fabsf(w[4 * j + 1])),
                           fmaxf(fabsf(w[4 * j + 2]), fabsf(w[4 * j + 3]))));
    }
#pragma unroll
    for (int o = 16; o > 0; o >>= 1)
        m = fmaxf(m, __shfl_xor_sync(0xFFFFFFFFu, m, o));

    const float s   = fmaxf(m, 1e-20f) * (1.0f / 127.0f);
    const float inv = 1.0f / s;

#pragma unroll
    for (int j = 0; j < 8; ++j) {
        int u0 = __float2int_rn(w[4 * j + 0] * inv) + 128;
        int u1 = __float2int_rn(w[4 * j + 1] * inv) + 128;
        int u2 = __float2int_rn(w[4 * j + 2] * inv) + 128;
        int u3 = __float2int_rn(w[4 * j + 3] * inv) + 128;
        u0 = min(255, max(0, u0)); u1 = min(255, max(0, u1));
        u2 = min(255, max(0, u2)); u3 = min(255, max(0, u3));
        g_q[(size_t)f * (FTOUT / 4) + j * 32 + lane] =
            (unsigned)u0 | ((unsigned)u1 << 8) | ((unsigned)u2 << 16) | ((unsigned)u3 << 24);
    }
    if (lane == 0) g_scale[f] = s;
}

// ---------------------------------------------------------------------------
// Kernel 2: 2 batches/CTA, 64 thr/batch, 16 cols/thread.
// Per-batch-side coefficients ms quantized to int8 (m8, scale mscale);
// per 4-feature group: 4x LDG.128, register byte-transpose (8 PRMT / 4 cols),
// dp4a.u32.s32 integer accumulation. Bias removed exactly in int:
// sum(m8*q) = I - 128*S8. All conversions exact (< 2^23).
// ---------------------------------------------------------------------------
__global__ __launch_bounds__(128) void nnue_q8_kernel(
    const float* __restrict__ values,
    const int*   __restrict__ stm_feat,
    const int*   __restrict__ nstm_feat,
    const float* __restrict__ b_ft,
    const float* __restrict__ b_fft,
    const float* __restrict__ W_out,
    const float* __restrict__ b_out,
    float*       __restrict__ out)
{
    __shared__ int   s_off[128];   // word offset per slot (group-of-4 aligned)
    __shared__ int   s_m8w[32];    // packed int8 coeffs, 4 per word
    __shared__ int   s_S8[4];      // per (batch,side) sum of m8
    __shared__ float s_msc[4];     // per (batch,side) mscale
    __shared__ float s_red[4];     // epilogue partials per warp

    const int tid  = threadIdx.x;
    const int bsel = tid >> 6;                 // batch within CTA
    const int t    = tid & 63;                 // thread-in-batch

    // ---- staging: warp w = (bsel, side); lane = feature slot ----
    {
        const int w    = tid >> 5;             // 0..3 = bsel*2 + side
        const int side = w & 1;
        const int bb   = blockIdx.x * 2 + (w >> 1);
        const int lane = tid & 31;
        const int idx  = side ? nstm_feat[bb * FPP + lane] : stm_feat[bb * FPP + lane];
        const float ms = g_scale[idx] * values[bb * FPP + lane];

        float mq = fabsf(ms);
#pragma unroll
        for (int o = 16; o > 0; o >>= 1)
            mq = fmaxf(mq, __shfl_xor_sync(0xFFFFFFFFu, mq, o));
        mq = fmaxf(mq, 1e-30f);
        const float mscale = mq * (1.0f / 127.0f);
        int m8 = __float2int_rn(ms * (127.0f / mq));
        m8 = min(127, max(-127, m8));

        s_off[tid] = idx * (FTOUT / 4);
        ((char*)s_m8w)[tid] = (char)m8;

        int S8 = m8;
#pragma unroll
        for (int o = 16; o > 0; o >>= 1)
            S8 += __shfl_xor_sync(0xFFFFFFFFu, S8, o);
        if (lane == 0) { s_S8[w] = S8; s_msc[w] = mscale; }
    }
    __syncthreads();

    const int wbase = t * 4;                   // first word of this thread's 16 cols
    const int c     = t * 16;                  // column base

    int acc_s[16], acc_n[16];
#pragma unroll
    for (int j = 0; j < 16; ++j) { acc_s[j] = 0; acc_n[j] = 0; }

#pragma unroll 4
    for (int g = 0; g < 8; ++g) {
        // stm side (slots 0..31)
        {
            const int4 off = *(const int4*)(s_off + bsel * 64 + g * 4);
            const unsigned mv = (unsigned)s_m8w[bsel * 16 + g];
            const uint4 w0 = *(const uint4*)(g_q + off.x + wbase);
            const uint4 w1 = *(const uint4*)(g_q + off.y + wbase);
            const uint4 w2 = *(const uint4*)(g_q + off.z + wbase);
            const uint4 w3 = *(const uint4*)(g_q + off.w + wbase);
            TR_DP(w0.x, w1.x, w2.x, w3.x, mv, acc_s + 0);
            TR_DP(w0.y, w1.y, w2.y, w3.y, mv, acc_s + 4);
            TR_DP(w0.z, w1.z, w2.z, w3.z, mv, acc_s + 8);
            TR_DP(w0.w, w1.w, w2.w, w3.w, mv, acc_s + 12);
        }
        // nstm side (slots 32..63)
        {
            const int4 off = *(const int4*)(s_off + bsel * 64 + 32 + g * 4);
            const unsigned mv = (unsigned)s_m8w[bsel * 16 + 8 + g];
            const uint4 w0 = *(const uint4*)(g_q + off.x + wbase);
            const uint4 w1 = *(const uint4*)(g_q + off.y + wbase);
            const uint4 w2 = *(const uint4*)(g_q + off.z + wbase);
            const uint4 w3 = *(const uint4*)(g_q + off.w + wbase);
            TR_DP(w0.x, w1.x, w2.x, w3.x, mv, acc_n + 0);
            TR_DP(w0.y, w1.y, w2.y, w3.y, mv, acc_n + 4);
            TR_DP(w0.z, w1.z, w2.z, w3.z, mv, acc_n + 8);
            TR_DP(w0.w, w1.w, w2.w, w3.w, mv, acc_n + 12);
        }
    }

    const int   S8s = s_S8[bsel * 2 + 0] * 128;
    const int   S8n = s_S8[bsel * 2 + 1] * 128;
    const float mss = s_msc[bsel * 2 + 0];
    const float msn = s_msc[bsel * 2 + 1];

    // Epilogue: dequant + bias + clip(0,1) + dot with W_out ([stm|nstm]).
    float partial = 0.f;
#pragma unroll
    for (int q = 0; q < 4; ++q) {
        const float4 bf   = *(const float4*)(b_ft  + c + 4 * q);
        const float4 bg   = *(const float4*)(b_fft + c + 4 * q);
        const float4 wo_s = *(const float4*)(W_out + c + 4 * q);
        const float4 wo_n = *(const float4*)(W_out + FTOUT + c + 4 * q);
        const float bias[4] = {bf.x + bg.x, bf.y + bg.y, bf.z + bg.z, bf.w + bg.w};
        const float wos[4]  = {wo_s.x, wo_s.y, wo_s.z, wo_s.w};
        const float won[4]  = {wo_n.x, wo_n.y, wo_n.z, wo_n.w};
#pragma unroll
        for (int i = 0; i < 4; ++i) {
            const int j = 4 * q + i;
            const float fs = (float)(acc_s[j] - S8s);   // exact, |.| < 2^23
            const float fn = (float)(acc_n[j] - S8n);
            const float hs = fminf(fmaxf(fmaf(fs, mss, bias[i]), 0.f), 1.f);
            const float hn = fminf(fmaxf(fmaf(fn, msn, bias[i]), 0.f), 1.f);
            partial = fmaf(hs, wos[i], fmaf(hn, won[i], partial));
        }
    }

#pragma unroll
    for (int o = 16; o > 0; o >>= 1)
        partial += __shfl_down_sync(0xFFFFFFFFu, partial, o);
    if ((tid & 31) == 0) s_red[tid >> 5] = partial;
    __syncthreads();
    if (t == 0) {
        const float x = s_red[bsel * 2] + s_red[bsel * 2 + 1] + b_out[0];
        out[blockIdx.x * 2 + bsel] = 1.f / (1.f + expf(-x));
    }
}

// ---------------------------------------------------------------------------
// Launch wrapper. Input order: values, stm_feat, nstm_feat, batch_idx,
// W_ft, b_ft, W_fft, b_fft, W_out, b_out, size.
// ---------------------------------------------------------------------------
extern "C" void kernel_launch(void* const* d_in, const int* in_sizes, int n_in,
                              void* d_out, int out_size) {
    const float* values    = (const float*)d_in[0];
    const int*   stm_feat  = (const int*)  d_in[1];
    const int*   nstm_feat = (const int*)  d_in[2];
    // d_in[3] = batch_idx (unused)
    const float* W_ft      = (const float*)d_in[4];
    const float* b_ft      = (const float*)d_in[5];
    const float* W_fft     = (const float*)d_in[6];
    const float* b_fft     = (const float*)d_in[7];
    const float* W_out     = (const float*)d_in[8];
    const float* b_out     = (const float*)d_in[9];
    float*       out       = (float*)d_out;

    const int B = out_size;  // 8192

    fuse_q8_kernel<<<NFEAT / 8, 256>>>(W_ft, W_fft);
    nnue_q8_kernel<<<B / 2, 128>>>(values, stm_feat, nstm_feat,
                                   b_ft, b_fft, W_out, b_out, out);
}